// round 15
// baseline (speedup 1.0000x reference)
#include <cuda_runtime.h>
#include <math_constants.h>

// GraphPoolMol: masked neighborhood max-pool over graph Laplacian sparsity.
// B=64, MAX_ATOM=128, N_FEAT=128.
// out[b,i,f] = max_{j: L[b,i,j]!=0, j<n, i<n} x[b,j,f]; 0 if i>=n.
// diag(L)=1 => for i<n the mask contains j=i (cnt>=1), so the reference's
// "no neighbor" fallback never fires for valid rows, and loading the self
// row as padding never changes the max.
//
// Warp-per-row. 256-thread blocks (8 rows of one batch), grid=1024, and
// __launch_bounds__(256,8) -> regs<=32, 8 blocks/SM, single wave.
// Gather: lane-parallel nth-bit extraction with self-row padding at lanes
// >= cnt (no clamps in the inner loop), exact dynamic load count, MLP-4.

#define AT 128
#define NF 128
#define THREADS 256

__device__ __forceinline__ float4 fmax4(float4 a, float4 b) {
    return make_float4(fmaxf(a.x, b.x), fmaxf(a.y, b.y),
                       fmaxf(a.z, b.z), fmaxf(a.w, b.w));
}

// Position of the r-th (0-indexed) set bit of m; in-range garbage when
// r >= popc(m) (those lanes are overridden with the self row).
__device__ __forceinline__ int nth_bit(unsigned m, int r) {
    int j = 0, c;
    c = __popc(m & 0xFFFFu); if (r >= c) { r -= c; m >>= 16; j = 16; }
    c = __popc(m & 0xFFu);   if (r >= c) { r -= c; m >>= 8;  j += 8; }
    c = __popc(m & 0xFu);    if (r >= c) { r -= c; m >>= 4;  j += 4; }
    c = __popc(m & 0x3u);    if (r >= c) { r -= c; m >>= 2;  j += 2; }
    c = (int)(m & 1u);       if (r >= c) {                   j += 1; }
    return j;
}

__global__ __launch_bounds__(THREADS, 8)
void graph_pool_mol_kernel(const float* __restrict__ xg,
                           const float* __restrict__ Lg,
                           const int* __restrict__ mol_slice,
                           float* __restrict__ outg)
{
    const int b    = blockIdx.x >> 4;              // batch (16 blocks each)
    const int i    = ((blockIdx.x & 15) << 3) + (threadIdx.x >> 5); // row
    const int lane = threadIdx.x & 31;

    // Issue both long-latency loads before anything depends on either.
    const int n = __ldg(mol_slice + 2 * b);        // mol_slice[b,0] = n_atoms
    const float4 Lv = __ldg(reinterpret_cast<const float4*>(
                                Lg + ((size_t)b * AT + i) * AT) + lane);

    float4* outr = reinterpret_cast<float4*>(outg) + ((size_t)b * AT + i) * 32;

    if (i >= n) {                                  // padded row
        outr[lane] = make_float4(0.f, 0.f, 0.f, 0.f);
        return;
    }

    // ---- Warp-uniform 128-bit mask (ballot word q: col = 4*bit + q) -------
    const int j0 = 4 * lane;
    const unsigned m0 = __ballot_sync(0xffffffffu, (Lv.x != 0.f) && (j0 + 0 < n));
    const unsigned m1 = __ballot_sync(0xffffffffu, (Lv.y != 0.f) && (j0 + 1 < n));
    const unsigned m2 = __ballot_sync(0xffffffffu, (Lv.z != 0.f) && (j0 + 2 < n));
    const unsigned m3 = __ballot_sync(0xffffffffu, (Lv.w != 0.f) && (j0 + 3 < n));

    const int c0 = __popc(m0), c1 = __popc(m1), c2 = __popc(m2);
    const int cnt = c0 + c1 + c2 + __popc(m3);     // >= 1 (diagonal)

    const float4* xb = reinterpret_cast<const float4*>(xg + (size_t)b * AT * NF);
    float4 acc0 = make_float4(-CUDART_INF_F, -CUDART_INF_F,
                              -CUDART_INF_F, -CUDART_INF_F);
    float4 acc1 = acc0;

    int done = 0;
    while (done < cnt) {                           // one pass unless cnt > 32
        // Lane s extracts the (done+s)-th set column; lanes past cnt get the
        // self row i (harmless padding for max -> clamp-free inner loop).
        const int t = done + lane;
        int tt = t;
        unsigned m = m0; int q = 0;
        if (tt >= c0) { tt -= c0; m = m1; q = 1;
            if (tt >= c1) { tt -= c1; m = m2; q = 2;
                if (tt >= c2) { tt -= c2; m = m3; q = 3; } } }
        int jmine = 4 * nth_bit(m, min(tt, 31)) + q;   // in [0,127]
        jmine = (t < cnt) ? jmine : i;                 // self-row padding

        const int cm = min(cnt - done, 32);
        // Exact load count (rounded to 4): padding lanes supply the self row.
        for (int kb = 0; kb < cm; kb += 4) {
            const int ja = __shfl_sync(0xffffffffu, jmine, kb + 0);
            const int jb = __shfl_sync(0xffffffffu, jmine, kb + 1);
            const int jc = __shfl_sync(0xffffffffu, jmine, kb + 2);
            const int jd = __shfl_sync(0xffffffffu, jmine, kb + 3);
            const float4 va = __ldg(xb + ja * 32 + lane);
            const float4 vb = __ldg(xb + jb * 32 + lane);
            const float4 vc = __ldg(xb + jc * 32 + lane);
            const float4 vd = __ldg(xb + jd * 32 + lane);
            acc0 = fmax4(acc0, va);
            acc1 = fmax4(acc1, vb);
            acc0 = fmax4(acc0, vc);
            acc1 = fmax4(acc1, vd);
        }
        done += cm;
    }

    outr[lane] = fmax4(acc0, acc1);
}

extern "C" void kernel_launch(void* const* d_in, const int* in_sizes, int n_in,
                              void* d_out, int out_size)
{
    const float* node_features = (const float*)d_in[0];
    const float* laplacian     = (const float*)d_in[1];
    const int*   mol_slice     = (const int*)d_in[2];
    // d_in[3] = l_slice (unused)

    float* out = (float*)d_out;

    const int B = 64;
    const int blocks = B * (AT / 8);               // 1024 blocks, 8 rows each
    graph_pool_mol_kernel<<<blocks, THREADS>>>(
        node_features, laplacian, mol_slice, out);
}

// round 16
// speedup vs baseline: 1.0036x; 1.0036x over previous
#include <cuda_runtime.h>
#include <math_constants.h>

// GraphPoolMol: masked neighborhood max-pool over graph Laplacian sparsity.
// B=64, MAX_ATOM=128, N_FEAT=128.
// out[b,i,f] = max_{j: L[b,i,j]!=0, j<n, i<n} x[b,j,f]; 0 if i>=n.
// diag(L)=1 => for i<n the mask contains j=i (cnt>=1), so the reference's
// "no neighbor" fallback never fires for valid rows.
//
// Warp-per-row, 256-thread blocks, grid=1024 (16 blocks per batch).
// LOAD BALANCE: block k of a batch owns rows {k, k+16, ..., k+112} (stride
// 16), so valid rows (i < n) spread evenly over all blocks -> every block
// carries equal work instead of half the blocks exiting instantly.

#define AT 128
#define NF 128
#define THREADS 256

__device__ __forceinline__ float4 fmax4(float4 a, float4 b) {
    return make_float4(fmaxf(a.x, b.x), fmaxf(a.y, b.y),
                       fmaxf(a.z, b.z), fmaxf(a.w, b.w));
}

// Position of the r-th (0-indexed) set bit of m; in-range garbage when
// r >= popc(m) (those lanes are never consumed).
__device__ __forceinline__ int nth_bit(unsigned m, int r) {
    int j = 0, c;
    c = __popc(m & 0xFFFFu); if (r >= c) { r -= c; m >>= 16; j = 16; }
    c = __popc(m & 0xFFu);   if (r >= c) { r -= c; m >>= 8;  j += 8; }
    c = __popc(m & 0xFu);    if (r >= c) { r -= c; m >>= 4;  j += 4; }
    c = __popc(m & 0x3u);    if (r >= c) { r -= c; m >>= 2;  j += 2; }
    c = (int)(m & 1u);       if (r >= c) {                   j += 1; }
    return j;
}

__global__ __launch_bounds__(THREADS, 6)
void graph_pool_mol_kernel(const float* __restrict__ xg,
                           const float* __restrict__ Lg,
                           const int* __restrict__ mol_slice,
                           float* __restrict__ outg)
{
    const int b    = blockIdx.x >> 4;              // batch (16 blocks each)
    const int k    = blockIdx.x & 15;              // block slot within batch
    const int wid  = threadIdx.x >> 5;             // 0..7
    const int i    = k + (wid << 4);               // interleaved row: k+16*wid
    const int lane = threadIdx.x & 31;

    // Issue both long-latency loads before anything depends on either.
    const int n = __ldg(mol_slice + 2 * b);        // mol_slice[b,0] = n_atoms
    const float4 Lv = __ldg(reinterpret_cast<const float4*>(
                                Lg + ((size_t)b * AT + i) * AT) + lane);

    float4* outr = reinterpret_cast<float4*>(outg) + ((size_t)b * AT + i) * 32;

    if (i >= n) {                                  // padded row
        outr[lane] = make_float4(0.f, 0.f, 0.f, 0.f);
        return;
    }

    // ---- Warp-uniform 128-bit mask (ballot word q: col = 4*bit + q) -------
    const int j0 = 4 * lane;
    const unsigned m0 = __ballot_sync(0xffffffffu, (Lv.x != 0.f) && (j0 + 0 < n));
    const unsigned m1 = __ballot_sync(0xffffffffu, (Lv.y != 0.f) && (j0 + 1 < n));
    const unsigned m2 = __ballot_sync(0xffffffffu, (Lv.z != 0.f) && (j0 + 2 < n));
    const unsigned m3 = __ballot_sync(0xffffffffu, (Lv.w != 0.f) && (j0 + 3 < n));

    const int c0 = __popc(m0), c1 = __popc(m1), c2 = __popc(m2);
    const int cnt = c0 + c1 + c2 + __popc(m3);     // >= 1 (diagonal)

    const float4* xb = reinterpret_cast<const float4*>(xg + (size_t)b * AT * NF);
    float4 acc0 = make_float4(-CUDART_INF_F, -CUDART_INF_F,
                              -CUDART_INF_F, -CUDART_INF_F);
    float4 acc1 = acc0;

    int done = 0;
    while (done < cnt) {                           // one pass unless cnt > 32
        // Lane s extracts the (done+s)-th set column.
        int t = done + lane;
        unsigned m = m0; int q = 0;
        if (t >= c0) { t -= c0; m = m1; q = 1;
            if (t >= c1) { t -= c1; m = m2; q = 2;
                if (t >= c2) { t -= c2; m = m3; q = 3; } } }
        const int jmine = 4 * nth_bit(m, min(t, 31)) + q;   // in [0,127]

        const int cm = min(cnt - done, 32);
        for (int kb = 0; kb < cm; kb += 4) {
            // Clamped source lane repeats the last valid neighbor (harmless).
            const int ja = __shfl_sync(0xffffffffu, jmine, min(kb + 0, cm - 1));
            const int jb = __shfl_sync(0xffffffffu, jmine, min(kb + 1, cm - 1));
            const int jc = __shfl_sync(0xffffffffu, jmine, min(kb + 2, cm - 1));
            const int jd = __shfl_sync(0xffffffffu, jmine, min(kb + 3, cm - 1));
            const float4 va = __ldg(xb + ja * 32 + lane);
            const float4 vb = __ldg(xb + jb * 32 + lane);
            const float4 vc = __ldg(xb + jc * 32 + lane);
            const float4 vd = __ldg(xb + jd * 32 + lane);
            acc0 = fmax4(acc0, va);
            acc1 = fmax4(acc1, vb);
            acc0 = fmax4(acc0, vc);
            acc1 = fmax4(acc1, vd);
        }
        done += cm;
    }

    outr[lane] = fmax4(acc0, acc1);
}

extern "C" void kernel_launch(void* const* d_in, const int* in_sizes, int n_in,
                              void* d_out, int out_size)
{
    const float* node_features = (const float*)d_in[0];
    const float* laplacian     = (const float*)d_in[1];
    const int*   mol_slice     = (const int*)d_in[2];
    // d_in[3] = l_slice (unused)

    float* out = (float*)d_out;

    const int B = 64;
    const int blocks = B * 16;                     // 1024 blocks, 8 rows each
    graph_pool_mol_kernel<<<blocks, THREADS>>>(
        node_features, laplacian, mol_slice, out);
}

// round 17
// speedup vs baseline: 1.0072x; 1.0036x over previous
#include <cuda_runtime.h>
#include <math_constants.h>

// GraphPoolMol: masked neighborhood max-pool over graph Laplacian sparsity.
// B=64, MAX_ATOM=128, N_FEAT=128.
// out[b,i,f] = max_{j: L[b,i,j]!=0, j<n, i<n} x[b,j,f]; 0 if i>=n.
// diag(L)=1 => for i<n the mask contains j=i (cnt>=1), so the reference's
// "no neighbor" fallback never fires for valid rows, and loading the self
// row as padding never changes the max.
//
// Warp-per-row, 256-thread blocks, grid=1024, rows interleaved (stride 16)
// across a batch's 16 blocks for balance. Gather sized to the REAL cnt
// distribution (mean ~7.3): cnt<=4 -> one 4-load window, cnt<=8 -> one
// 8-load window, else 8 + exact 4-load remainder. Self-row padding makes
// every window clamp-free.

#define AT 128
#define NF 128
#define THREADS 256

__device__ __forceinline__ float4 fmax4(float4 a, float4 b) {
    return make_float4(fmaxf(a.x, b.x), fmaxf(a.y, b.y),
                       fmaxf(a.z, b.z), fmaxf(a.w, b.w));
}

// Position of the r-th (0-indexed) set bit of m; in-range garbage when
// r >= popc(m) (those lanes are overridden with the self row).
__device__ __forceinline__ int nth_bit(unsigned m, int r) {
    int j = 0, c;
    c = __popc(m & 0xFFFFu); if (r >= c) { r -= c; m >>= 16; j = 16; }
    c = __popc(m & 0xFFu);   if (r >= c) { r -= c; m >>= 8;  j += 8; }
    c = __popc(m & 0xFu);    if (r >= c) { r -= c; m >>= 4;  j += 4; }
    c = __popc(m & 0x3u);    if (r >= c) { r -= c; m >>= 2;  j += 2; }
    c = (int)(m & 1u);       if (r >= c) {                   j += 1; }
    return j;
}

__global__ __launch_bounds__(THREADS, 5)
void graph_pool_mol_kernel(const float* __restrict__ xg,
                           const float* __restrict__ Lg,
                           const int* __restrict__ mol_slice,
                           float* __restrict__ outg)
{
    const int b    = blockIdx.x >> 4;              // batch (16 blocks each)
    const int k    = blockIdx.x & 15;              // block slot within batch
    const int wid  = threadIdx.x >> 5;             // 0..7
    const int i    = k + (wid << 4);               // interleaved row
    const int lane = threadIdx.x & 31;

    // Issue both long-latency loads before anything depends on either.
    const int n = __ldg(mol_slice + 2 * b);        // mol_slice[b,0] = n_atoms
    const float4 Lv = __ldg(reinterpret_cast<const float4*>(
                                Lg + ((size_t)b * AT + i) * AT) + lane);

    float4* outr = reinterpret_cast<float4*>(outg) + ((size_t)b * AT + i) * 32;

    if (i >= n) {                                  // padded row
        outr[lane] = make_float4(0.f, 0.f, 0.f, 0.f);
        return;
    }

    // ---- Warp-uniform 128-bit mask (ballot word q: col = 4*bit + q) -------
    const int j0 = 4 * lane;
    const unsigned m0 = __ballot_sync(0xffffffffu, (Lv.x != 0.f) && (j0 + 0 < n));
    const unsigned m1 = __ballot_sync(0xffffffffu, (Lv.y != 0.f) && (j0 + 1 < n));
    const unsigned m2 = __ballot_sync(0xffffffffu, (Lv.z != 0.f) && (j0 + 2 < n));
    const unsigned m3 = __ballot_sync(0xffffffffu, (Lv.w != 0.f) && (j0 + 3 < n));

    const int c0 = __popc(m0), c1 = __popc(m1), c2 = __popc(m2);
    const int cnt = c0 + c1 + c2 + __popc(m3);     // >= 1 (diagonal)

    const float4* xb = reinterpret_cast<const float4*>(xg + (size_t)b * AT * NF);
    float4 acc0 = make_float4(-CUDART_INF_F, -CUDART_INF_F,
                              -CUDART_INF_F, -CUDART_INF_F);
    float4 acc1 = acc0;

    int done = 0;
    while (done < cnt) {                           // one pass unless cnt > 32
        // Lane s extracts the (done+s)-th set column; lanes past cnt supply
        // the self row i (harmless for max -> clamp-free windows).
        const int t = done + lane;
        int tt = t;
        unsigned m = m0; int q = 0;
        if (tt >= c0) { tt -= c0; m = m1; q = 1;
            if (tt >= c1) { tt -= c1; m = m2; q = 2;
                if (tt >= c2) { tt -= c2; m = m3; q = 3; } } }
        int jmine = 4 * nth_bit(m, min(tt, 31)) + q;   // in [0,127]
        jmine = (t < cnt) ? jmine : i;                 // self-row padding

        const int cm = min(cnt - done, 32);

        if (cm <= 4) {
            // One 4-load window.
            const int ja = __shfl_sync(0xffffffffu, jmine, 0);
            const int jb = __shfl_sync(0xffffffffu, jmine, 1);
            const int jc = __shfl_sync(0xffffffffu, jmine, 2);
            const int jd = __shfl_sync(0xffffffffu, jmine, 3);
            const float4 va = __ldg(xb + ja * 32 + lane);
            const float4 vb = __ldg(xb + jb * 32 + lane);
            const float4 vc = __ldg(xb + jc * 32 + lane);
            const float4 vd = __ldg(xb + jd * 32 + lane);
            acc0 = fmax4(acc0, va);
            acc1 = fmax4(acc1, vb);
            acc0 = fmax4(acc0, vc);
            acc1 = fmax4(acc1, vd);
        } else {
            // One 8-load window covers cnt<=8 outright.
            const int j8a = __shfl_sync(0xffffffffu, jmine, 0);
            const int j8b = __shfl_sync(0xffffffffu, jmine, 1);
            const int j8c = __shfl_sync(0xffffffffu, jmine, 2);
            const int j8d = __shfl_sync(0xffffffffu, jmine, 3);
            const int j8e = __shfl_sync(0xffffffffu, jmine, 4);
            const int j8f = __shfl_sync(0xffffffffu, jmine, 5);
            const int j8g = __shfl_sync(0xffffffffu, jmine, 6);
            const int j8h = __shfl_sync(0xffffffffu, jmine, 7);
            const float4 v0 = __ldg(xb + j8a * 32 + lane);
            const float4 v1 = __ldg(xb + j8b * 32 + lane);
            const float4 v2 = __ldg(xb + j8c * 32 + lane);
            const float4 v3 = __ldg(xb + j8d * 32 + lane);
            const float4 v4 = __ldg(xb + j8e * 32 + lane);
            const float4 v5 = __ldg(xb + j8f * 32 + lane);
            const float4 v6 = __ldg(xb + j8g * 32 + lane);
            const float4 v7 = __ldg(xb + j8h * 32 + lane);
            acc0 = fmax4(acc0, v0);
            acc1 = fmax4(acc1, v1);
            acc0 = fmax4(acc0, v2);
            acc1 = fmax4(acc1, v3);
            acc0 = fmax4(acc0, v4);
            acc1 = fmax4(acc1, v5);
            acc0 = fmax4(acc0, v6);
            acc1 = fmax4(acc1, v7);

            // Exact remainder in 4-load windows (only dense rows).
            for (int kb = 8; kb < cm; kb += 4) {
                const int ja = __shfl_sync(0xffffffffu, jmine, kb + 0);
                const int jb = __shfl_sync(0xffffffffu, jmine, kb + 1);
                const int jc = __shfl_sync(0xffffffffu, jmine, kb + 2);
                const int jd = __shfl_sync(0xffffffffu, jmine, kb + 3);
                const float4 va = __ldg(xb + ja * 32 + lane);
                const float4 vb = __ldg(xb + jb * 32 + lane);
                const float4 vc = __ldg(xb + jc * 32 + lane);
                const float4 vd = __ldg(xb + jd * 32 + lane);
                acc0 = fmax4(acc0, va);
                acc1 = fmax4(acc1, vb);
                acc0 = fmax4(acc0, vc);
                acc1 = fmax4(acc1, vd);
            }
        }
        done += cm;
    }

    outr[lane] = fmax4(acc0, acc1);
}

extern "C" void kernel_launch(void* const* d_in, const int* in_sizes, int n_in,
                              void* d_out, int out_size)
{
    const float* node_features = (const float*)d_in[0];
    const float* laplacian     = (const float*)d_in[1];
    const int*   mol_slice     = (const int*)d_in[2];
    // d_in[3] = l_slice (unused)

    float* out = (float*)d_out;

    const int B = 64;
    const int blocks = B * 16;                     // 1024 blocks
    graph_pool_mol_kernel<<<blocks, THREADS>>>(
        node_features, laplacian, mol_slice, out);
}